// round 16
// baseline (speedup 1.0000x reference)
#include <cuda_runtime.h>
#include <cstdint>

#define BB 2
#define LL 2048
#define HH 16
#define EE 64
#define NKT 32

// fp16x2 frag-major packed operands (layouts unchanged from R12/R13).
__device__ uint4 g_Qh[BB * HH * 256 * 2 * 32];
__device__ uint4 g_Kh[BB * HH * 256 * 2 * 32];
__device__ uint4 g_Vh[BB * HH * NKT * 16 * 32];

#define LOG2E 1.4426950408889634f
#define SCL2  0.18033688011112042592f   // 0.125 * log2(e)

__device__ __forceinline__ uint32_t packh2(float lo, float hi) {
    uint32_t r;
    asm("cvt.rn.f16x2.f32 %0, %1, %2;" : "=r"(r) : "f"(hi), "f"(lo));
    return r;
}
__device__ __forceinline__ float ex2f(float x) {
    float o;
    asm("ex2.approx.f32 %0, %1;" : "=f"(o) : "f"(x));
    return o;
}
// Non-volatile: pure register computation; ptxas may interleave chains.
__device__ __forceinline__ void mma16(float c[4], uint32_t a0, uint32_t a1,
                                      uint32_t a2, uint32_t a3,
                                      uint32_t b0, uint32_t b1) {
    asm("mma.sync.aligned.m16n8k16.row.col.f32.f16.f16.f32 "
        "{%0,%1,%2,%3}, {%4,%5,%6,%7}, {%8,%9}, {%0,%1,%2,%3};"
        : "+f"(c[0]), "+f"(c[1]), "+f"(c[2]), "+f"(c[3])
        : "r"(a0), "r"(a1), "r"(a2), "r"(a3), "r"(b0), "r"(b1));
}

// ---------------------------------------------------------------------------
// Fused prepass (unchanged — proven).
// ---------------------------------------------------------------------------
__global__ void prep_kernel(const float* __restrict__ q,
                            const float* __restrict__ k,
                            const float* __restrict__ v) {
    __shared__ float sq[64 * 65];
    __shared__ float sk[64 * 65];
    const int kt = blockIdx.x, h = blockIdx.y, b = blockIdx.z;
    const int bh = b * HH + h;
    const int tid = threadIdx.x;

    #pragma unroll
    for (int it = 0; it < 4; it++) {
        int i = it * 256 + tid;
        int j = i >> 4, e4 = i & 15;
        int l = kt * 64 + j;
        size_t gidx = ((size_t)(b * LL + l) * HH + h) * 16 + e4;
        float4 vq = ((const float4*)q)[gidx];
        float4 vk = ((const float4*)k)[gidx];
        if (e4 < 8) {
            float i0 = (float)(e4 * 2);
            const float NEG_L2 = -0.83048202372184058696f;  // -log2(10000)/16
            float s0, c0, s1, c1;
            sincosf((float)l * exp2f(i0 * NEG_L2), &s0, &c0);
            sincosf((float)l * exp2f((i0 + 1.0f) * NEG_L2), &s1, &c1);
            float4 o;
            o.x = c0 * vq.x - s0 * vq.y;  o.y = c0 * vq.y + s0 * vq.x;
            o.z = c1 * vq.z - s1 * vq.w;  o.w = c1 * vq.w + s1 * vq.z;
            vq = o;
            o.x = c0 * vk.x - s0 * vk.y;  o.y = c0 * vk.y + s0 * vk.x;
            o.z = c1 * vk.z - s1 * vk.w;  o.w = c1 * vk.w + s1 * vk.z;
            vk = o;
        }
        int e = e4 * 4;
        sq[j * 65 + e + 0] = vq.x; sq[j * 65 + e + 1] = vq.y;
        sq[j * 65 + e + 2] = vq.z; sq[j * 65 + e + 3] = vq.w;
        sk[j * 65 + e + 0] = vk.x; sk[j * 65 + e + 1] = vk.y;
        sk[j * 65 + e + 2] = vk.z; sk[j * 65 + e + 3] = vk.w;
    }
    __syncthreads();

    uint4* Qh = g_Qh + ((size_t)bh * 256 + kt * 8) * 2 * 32;
    uint4* Kh = g_Kh + ((size_t)bh * 256 + kt * 8) * 2 * 32;
    #pragma unroll
    for (int it = 0; it < 2; it++) {
        int i = it * 256 + tid;
        int lane = i & 31, x = i >> 5;       // x = grp*2 + kbp2
        int grp = x >> 1, kbp2 = x & 1;
        int g = lane >> 2, t = lane & 3;
        const float* s = sq + (grp * 8 + g) * 65 + kbp2 * 32 + 2 * t;
        uint4 o;
        o.x = packh2(s[0],  s[1]);
        o.y = packh2(s[8],  s[9]);
        o.z = packh2(s[16], s[17]);
        o.w = packh2(s[24], s[25]);
        Qh[x * 32 + lane] = o;
        const float* s2 = sk + (grp * 8 + g) * 65 + kbp2 * 32 + 2 * t;
        o.x = packh2(s2[0],  s2[1]);
        o.y = packh2(s2[8],  s2[9]);
        o.z = packh2(s2[16], s2[17]);
        o.w = packh2(s2[24], s2[25]);
        Kh[x * 32 + lane] = o;
    }
    __syncthreads();

    const float* Vg = v + ((size_t)(b * LL + kt * 64) * HH + h) * EE;
    #pragma unroll
    for (int it = 0; it < 4; it++) {
        int i = it * 256 + tid;
        int j = i >> 4, e = (i & 15) * 4;
        float4 w = *(const float4*)(Vg + (size_t)j * (HH * EE) + e);
        sq[j * 65 + e + 0] = w.x; sq[j * 65 + e + 1] = w.y;
        sq[j * 65 + e + 2] = w.z; sq[j * 65 + e + 3] = w.w;
    }
    __syncthreads();

    uint4* Vh = g_Vh + ((size_t)bh * NKT + kt) * 16 * 32;
    #pragma unroll
    for (int it = 0; it < 2; it++) {
        int i = it * 256 + tid;
        int lane = i & 31, x = i >> 5;       // x = nbp*4 + db2
        int nbp = x >> 2, db2 = x & 3;
        int g = lane >> 2, t = lane & 3;
        const float* v0 = sq + (16 * nbp + 2 * t) * 65 + 16 * db2 + g;
        uint4 o;
        o.x = packh2(v0[0],        v0[65]);
        o.y = packh2(v0[8 * 65],   v0[9 * 65]);
        o.z = packh2(v0[8],        v0[65 + 8]);
        o.w = packh2(v0[8 * 65 + 8], v0[9 * 65 + 8]);
        Vh[x * 32 + lane] = o;
    }
}

// QK for one 8-key block via TWO independent 2-deep chains merged by FADD —
// halves the serial HMMA latency vs a 4-deep chain.
__device__ __forceinline__ void qk_split(
    const uint32_t (&qa)[4][4], const uint4* __restrict__ Kt, int nb,
    float (&c)[4])
{
    uint4 ka = Kt[nb * 64], kb = Kt[nb * 64 + 32];
    float ce[4] = {0, 0, 0, 0}, co[4] = {0, 0, 0, 0};
    mma16(ce, qa[0][0], qa[0][1], qa[0][2], qa[0][3], ka.x, ka.y);
    mma16(co, qa[1][0], qa[1][1], qa[1][2], qa[1][3], ka.z, ka.w);
    mma16(ce, qa[2][0], qa[2][1], qa[2][2], qa[2][3], kb.x, kb.y);
    mma16(co, qa[3][0], qa[3][1], qa[3][2], qa[3][3], kb.z, kb.w);
    #pragma unroll
    for (int i = 0; i < 4; i++) c[i] = ce[i] + co[i];
}

// ---------------------------------------------------------------------------
// One tile at one kt (R13 block structure, split-chain QK).
// ---------------------------------------------------------------------------
template <int NBPN>
__device__ __forceinline__ void tile_kt(
    int dep, int n0, const uint32_t (&qa)[4][4],
    const uint4* __restrict__ Kt, const uint4* __restrict__ Vt,
    float biasA, float biasB, int t,
    float (&oacc)[8][4], float& lsA, float& lsB)
{
    #pragma unroll
    for (int nbp = 0; nbp < NBPN; nbp++) {
        const int nb0 = 2 * nbp, nb1 = nb0 + 1;
        if (nb0 > dep) continue;              // warp-uniform prune
        const bool a1 = (nb1 <= dep);

        float c0[4], c1[4];
        qk_split(qa, Kt, nb0, c0);
        if (a1) qk_split(qa, Kt, nb1, c1);

        uint32_t pa0, pa1, pa2, pa3;
        {
            const int ci = nb0 * 8 + 2 * t;
            float p0 = (ci     <= n0) ? ex2f(fmaf(c0[0], SCL2, biasA)) : 0.0f;
            float p1 = (ci + 1 <= n0) ? ex2f(fmaf(c0[1], SCL2, biasA)) : 0.0f;
            float p2 = (ci     <= n0) ? ex2f(fmaf(c0[2], SCL2, biasB)) : 0.0f;
            float p3 = (ci + 1 <= n0) ? ex2f(fmaf(c0[3], SCL2, biasB)) : 0.0f;
            lsA += p0 + p1;
            lsB += p2 + p3;
            pa0 = packh2(p0, p1);
            pa1 = packh2(p2, p3);
        }
        if (a1) {
            const int ci = nb1 * 8 + 2 * t;
            float p0 = (ci     <= n0) ? ex2f(fmaf(c1[0], SCL2, biasA)) : 0.0f;
            float p1 = (ci + 1 <= n0) ? ex2f(fmaf(c1[1], SCL2, biasA)) : 0.0f;
            float p2 = (ci     <= n0) ? ex2f(fmaf(c1[2], SCL2, biasB)) : 0.0f;
            float p3 = (ci + 1 <= n0) ? ex2f(fmaf(c1[3], SCL2, biasB)) : 0.0f;
            lsA += p0 + p1;
            lsB += p2 + p3;
            pa2 = packh2(p0, p1);
            pa3 = packh2(p2, p3);
        } else {
            pa2 = 0u; pa3 = 0u;
        }

        #pragma unroll
        for (int db2 = 0; db2 < 4; db2++) {
            uint4 vv = Vt[(nbp * 4 + db2) * 32];
            mma16(oacc[2 * db2],     pa0, pa1, pa2, pa3, vv.x, vv.y);
            mma16(oacc[2 * db2 + 1], pa0, pa1, pa2, pa3, vv.z, vv.w);
        }
    }
}

// ---------------------------------------------------------------------------
// Main attention: balanced dual-tile warps (R13) with split-chain QK.
// 128 threads = 4 warps; warp w owns depth tiles {w, 7-w} -> 9 blocks/kt.
// ---------------------------------------------------------------------------
__global__ __launch_bounds__(128, 4)
void attn13(const float* __restrict__ bw, float* __restrict__ out) {
    const int tid  = threadIdx.x;
    const int lane = tid & 31;
    const int w    = tid >> 5;       // 0..3
    const int g    = lane >> 2;
    const int t    = lane & 3;
    const int qtb  = blockIdx.x;
    const int h    = blockIdx.y;
    const int b    = blockIdx.z;
    const int bh   = b * HH + h;
    const int l0   = qtb * 128;

    const float b2s = bw[HH + h] * LOG2E;
    const float b2d = bw[h] * LOG2E;

    const int dep0 = w;              // light tile
    const int dep1 = 7 - w;          // heavy tile
    const int n00  = 8 * dep0 + g;
    const int n01  = 8 * dep1 + g;

    uint32_t qa0[4][4], qa1[4][4];
    {
        const uint4* QA = g_Qh + ((size_t)bh * 256 + qtb * 16 + dep0) * 64 + lane;
        const uint4* QB = QA + 8 * 64;
        uint4 a0 = QA[0], a1 = QA[32], b0 = QB[0], b1 = QB[32];
        qa0[0][0] = a0.x; qa0[0][1] = b0.x; qa0[0][2] = a0.y; qa0[0][3] = b0.y;
        qa0[1][0] = a0.z; qa0[1][1] = b0.z; qa0[1][2] = a0.w; qa0[1][3] = b0.w;
        qa0[2][0] = a1.x; qa0[2][1] = b1.x; qa0[2][2] = a1.y; qa0[2][3] = b1.y;
        qa0[3][0] = a1.z; qa0[3][1] = b1.z; qa0[3][2] = a1.w; qa0[3][3] = b1.w;
    }
    {
        const uint4* QA = g_Qh + ((size_t)bh * 256 + qtb * 16 + dep1) * 64 + lane;
        const uint4* QB = QA + 8 * 64;
        uint4 a0 = QA[0], a1 = QA[32], b0 = QB[0], b1 = QB[32];
        qa1[0][0] = a0.x; qa1[0][1] = b0.x; qa1[0][2] = a0.y; qa1[0][3] = b0.y;
        qa1[1][0] = a0.z; qa1[1][1] = b0.z; qa1[1][2] = a0.w; qa1[1][3] = b0.w;
        qa1[2][0] = a1.x; qa1[2][1] = b1.x; qa1[2][2] = a1.y; qa1[2][3] = b1.y;
        qa1[3][0] = a1.z; qa1[3][1] = b1.z; qa1[3][2] = a1.w; qa1[3][3] = b1.w;
    }

    float o0[8][4], o1[8][4];
    #pragma unroll
    for (int db = 0; db < 8; db++)
        #pragma unroll
        for (int i = 0; i < 4; i++) { o0[db][i] = 0.0f; o1[db][i] = 0.0f; }
    float lsA0 = 0.0f, lsB0 = 0.0f, lsA1 = 0.0f, lsB1 = 0.0f;

    const uint4* Kf0 = g_Kh + (size_t)bh * 256 * 64 + lane;
    const uint4* Vf0 = g_Vh + (size_t)bh * NKT * 512 + lane;

    for (int kt = 0; kt < NKT; kt++) {
        const uint4* Kt = Kf0 + (size_t)kt * 8 * 64;
        const uint4* Vt = Vf0 + (size_t)kt * 512;
        const float biasA = (kt == 2 * qtb)     ? b2s : b2d;
        const float biasB = (kt == 2 * qtb + 1) ? b2s : b2d;

        tile_kt<2>(dep0, n00, qa0, Kt, Vt, biasA, biasB, t, o0, lsA0, lsB0);
        tile_kt<4>(dep1, n01, qa1, Kt, Vt, biasA, biasB, t, o1, lsA1, lsB1);
    }

    #pragma unroll
    for (int ti = 0; ti < 2; ti++) {
        float lsA = ti ? lsA1 : lsA0;
        float lsB = ti ? lsB1 : lsB0;
        lsA += __shfl_xor_sync(0xffffffffu, lsA, 1);
        lsA += __shfl_xor_sync(0xffffffffu, lsA, 2);
        lsB += __shfl_xor_sync(0xffffffffu, lsB, 1);
        lsB += __shfl_xor_sync(0xffffffffu, lsB, 2);
        const float invA = 1.0f / lsA;
        const float invB = 1.0f / lsB;
        float (*oacc)[4] = ti ? o1 : o0;
        const int dep = ti ? dep1 : dep0;
        const int rowA = l0 + 8 * dep + g;
        const int rowB = rowA + 64;
        #pragma unroll
        for (int db = 0; db < 8; db++) {
            float2 v0;
            v0.x = oacc[db][0] * invA;
            v0.y = oacc[db][1] * invA;
            *(float2*)(out + (((size_t)(b * LL + rowA)) * HH + h) * EE + db * 8 + 2 * t) = v0;
            float2 v1;
            v1.x = oacc[db][2] * invB;
            v1.y = oacc[db][3] * invB;
            *(float2*)(out + (((size_t)(b * LL + rowB)) * HH + h) * EE + db * 8 + 2 * t) = v1;
        }
    }
}

// ---------------------------------------------------------------------------
extern "C" void kernel_launch(void* const* d_in, const int* in_sizes, int n_in,
                              void* d_out, int out_size) {
    const float* q  = (const float*)d_in[0];
    const float* k  = (const float*)d_in[1];
    const float* v  = (const float*)d_in[2];
    const float* bw = (const float*)d_in[3];
    float* out = (float*)d_out;

    prep_kernel<<<dim3(NKT, HH, BB), 256>>>(q, k, v);

    dim3 grid(LL / 128, HH, BB);
    attn13<<<grid, 128>>>(bw, out);
}

// round 17
// speedup vs baseline: 1.5184x; 1.5184x over previous
#include <cuda_runtime.h>
#include <cstdint>

#define BB 2
#define LL 2048
#define HH 16
#define EE 64
#define NKT 32

// fp16x2 frag-major packed operands (layouts unchanged from R12/R13).
__device__ uint4 g_Qh[BB * HH * 256 * 2 * 32];
__device__ uint4 g_Kh[BB * HH * 256 * 2 * 32];
__device__ uint4 g_Vh[BB * HH * NKT * 16 * 32];

#define LOG2E 1.4426950408889634f
#define SCL2  0.18033688011112042592f   // 0.125 * log2(e)

__device__ __forceinline__ uint32_t packh2(float lo, float hi) {
    uint32_t r;
    asm("cvt.rn.f16x2.f32 %0, %1, %2;" : "=r"(r) : "f"(hi), "f"(lo));
    return r;
}
__device__ __forceinline__ float ex2f(float x) {
    float o;
    asm("ex2.approx.f32 %0, %1;" : "=f"(o) : "f"(x));
    return o;
}
// Non-volatile: pure register computation — ptxas may hoist/interleave the
// independent HMMA chains (QK-ahead pipeline + cross-tile overlap).
__device__ __forceinline__ void mma16(float c[4], uint32_t a0, uint32_t a1,
                                      uint32_t a2, uint32_t a3,
                                      uint32_t b0, uint32_t b1) {
    asm("mma.sync.aligned.m16n8k16.row.col.f32.f16.f16.f32 "
        "{%0,%1,%2,%3}, {%4,%5,%6,%7}, {%8,%9}, {%0,%1,%2,%3};"
        : "+f"(c[0]), "+f"(c[1]), "+f"(c[2]), "+f"(c[3])
        : "r"(a0), "r"(a1), "r"(a2), "r"(a3), "r"(b0), "r"(b1));
}

// ---------------------------------------------------------------------------
// Fused prepass; __sincosf (MUFU) replaces polynomial sincosf — angle <= 2048
// rad gives ~2.4e-4 abs error -> ~1e-4 score error, negligible vs threshold.
// ---------------------------------------------------------------------------
__global__ void prep_kernel(const float* __restrict__ q,
                            const float* __restrict__ k,
                            const float* __restrict__ v) {
    __shared__ float sq[64 * 65];
    __shared__ float sk[64 * 65];
    const int kt = blockIdx.x, h = blockIdx.y, b = blockIdx.z;
    const int bh = b * HH + h;
    const int tid = threadIdx.x;

    #pragma unroll
    for (int it = 0; it < 4; it++) {
        int i = it * 256 + tid;
        int j = i >> 4, e4 = i & 15;
        int l = kt * 64 + j;
        size_t gidx = ((size_t)(b * LL + l) * HH + h) * 16 + e4;
        float4 vq = ((const float4*)q)[gidx];
        float4 vk = ((const float4*)k)[gidx];
        if (e4 < 8) {
            float i0 = (float)(e4 * 2);
            const float NEG_L2 = -0.83048202372184058696f;  // -log2(10000)/16
            float s0, c0, s1, c1;
            __sincosf((float)l * exp2f(i0 * NEG_L2), &s0, &c0);
            __sincosf((float)l * exp2f((i0 + 1.0f) * NEG_L2), &s1, &c1);
            float4 o;
            o.x = c0 * vq.x - s0 * vq.y;  o.y = c0 * vq.y + s0 * vq.x;
            o.z = c1 * vq.z - s1 * vq.w;  o.w = c1 * vq.w + s1 * vq.z;
            vq = o;
            o.x = c0 * vk.x - s0 * vk.y;  o.y = c0 * vk.y + s0 * vk.x;
            o.z = c1 * vk.z - s1 * vk.w;  o.w = c1 * vk.w + s1 * vk.z;
            vk = o;
        }
        int e = e4 * 4;
        sq[j * 65 + e + 0] = vq.x; sq[j * 65 + e + 1] = vq.y;
        sq[j * 65 + e + 2] = vq.z; sq[j * 65 + e + 3] = vq.w;
        sk[j * 65 + e + 0] = vk.x; sk[j * 65 + e + 1] = vk.y;
        sk[j * 65 + e + 2] = vk.z; sk[j * 65 + e + 3] = vk.w;
    }
    __syncthreads();

    uint4* Qh = g_Qh + ((size_t)bh * 256 + kt * 8) * 2 * 32;
    uint4* Kh = g_Kh + ((size_t)bh * 256 + kt * 8) * 2 * 32;
    #pragma unroll
    for (int it = 0; it < 2; it++) {
        int i = it * 256 + tid;
        int lane = i & 31, x = i >> 5;       // x = grp*2 + kbp2
        int grp = x >> 1, kbp2 = x & 1;
        int g = lane >> 2, t = lane & 3;
        const float* s = sq + (grp * 8 + g) * 65 + kbp2 * 32 + 2 * t;
        uint4 o;
        o.x = packh2(s[0],  s[1]);
        o.y = packh2(s[8],  s[9]);
        o.z = packh2(s[16], s[17]);
        o.w = packh2(s[24], s[25]);
        Qh[x * 32 + lane] = o;
        const float* s2 = sk + (grp * 8 + g) * 65 + kbp2 * 32 + 2 * t;
        o.x = packh2(s2[0],  s2[1]);
        o.y = packh2(s2[8],  s2[9]);
        o.z = packh2(s2[16], s2[17]);
        o.w = packh2(s2[24], s2[25]);
        Kh[x * 32 + lane] = o;
    }
    __syncthreads();

    const float* Vg = v + ((size_t)(b * LL + kt * 64) * HH + h) * EE;
    #pragma unroll
    for (int it = 0; it < 4; it++) {
        int i = it * 256 + tid;
        int j = i >> 4, e = (i & 15) * 4;
        float4 w = *(const float4*)(Vg + (size_t)j * (HH * EE) + e);
        sq[j * 65 + e + 0] = w.x; sq[j * 65 + e + 1] = w.y;
        sq[j * 65 + e + 2] = w.z; sq[j * 65 + e + 3] = w.w;
    }
    __syncthreads();

    uint4* Vh = g_Vh + ((size_t)bh * NKT + kt) * 16 * 32;
    #pragma unroll
    for (int it = 0; it < 2; it++) {
        int i = it * 256 + tid;
        int lane = i & 31, x = i >> 5;       // x = nbp*4 + db2
        int nbp = x >> 2, db2 = x & 3;
        int g = lane >> 2, t = lane & 3;
        const float* v0 = sq + (16 * nbp + 2 * t) * 65 + 16 * db2 + g;
        uint4 o;
        o.x = packh2(v0[0],        v0[65]);
        o.y = packh2(v0[8 * 65],   v0[9 * 65]);
        o.z = packh2(v0[8],        v0[65 + 8]);
        o.w = packh2(v0[8 * 65 + 8], v0[9 * 65 + 8]);
        Vh[x * 32 + lane] = o;
    }
}

// ---- QK for one nbp pair: 4-8 mma into c0/c1 ----
__device__ __forceinline__ void qk_block(
    const uint32_t (&qa)[4][4], const uint4* __restrict__ Kt,
    int nbp, bool a1, float (&c0)[4], float (&c1)[4])
{
    const int nb0 = 2 * nbp;
    {
        uint4 k0 = Kt[nb0 * 64], k1 = Kt[nb0 * 64 + 32];
        mma16(c0, qa[0][0], qa[0][1], qa[0][2], qa[0][3], k0.x, k0.y);
        mma16(c0, qa[1][0], qa[1][1], qa[1][2], qa[1][3], k0.z, k0.w);
        mma16(c0, qa[2][0], qa[2][1], qa[2][2], qa[2][3], k1.x, k1.y);
        mma16(c0, qa[3][0], qa[3][1], qa[3][2], qa[3][3], k1.z, k1.w);
    }
    if (a1) {
        uint4 k0 = Kt[(nb0 + 1) * 64], k1 = Kt[(nb0 + 1) * 64 + 32];
        mma16(c1, qa[0][0], qa[0][1], qa[0][2], qa[0][3], k0.x, k0.y);
        mma16(c1, qa[1][0], qa[1][1], qa[1][2], qa[1][3], k0.z, k0.w);
        mma16(c1, qa[2][0], qa[2][1], qa[2][2], qa[2][3], k1.x, k1.y);
        mma16(c1, qa[3][0], qa[3][1], qa[3][2], qa[3][3], k1.z, k1.w);
    }
}

// ---------------------------------------------------------------------------
// One tile at one kt, software-pipelined (R14 structure).
// ---------------------------------------------------------------------------
template <int NBPN>
__device__ __forceinline__ void tile_kt_pipe(
    int dep, int n0, const uint32_t (&qa)[4][4],
    const uint4* __restrict__ Kt, const uint4* __restrict__ Vt,
    float biasA, float biasB, int t,
    float (&oacc)[8][4], float& lsA, float& lsB)
{
    float c0[4] = {0, 0, 0, 0}, c1[4] = {0, 0, 0, 0};
    qk_block(qa, Kt, 0, (1 <= dep), c0, c1);

    #pragma unroll
    for (int nbp = 0; nbp < NBPN; nbp++) {
        const int nb0 = 2 * nbp, nb1 = nb0 + 1;
        if (nb0 > dep) continue;              // tail-only skip
        const bool a1 = (nb1 <= dep);

        uint32_t pa0, pa1, pa2, pa3;
        {
            const int ci = nb0 * 8 + 2 * t;
            float p0 = (ci     <= n0) ? ex2f(fmaf(c0[0], SCL2, biasA)) : 0.0f;
            float p1 = (ci + 1 <= n0) ? ex2f(fmaf(c0[1], SCL2, biasA)) : 0.0f;
            float p2 = (ci     <= n0) ? ex2f(fmaf(c0[2], SCL2, biasB)) : 0.0f;
            float p3 = (ci + 1 <= n0) ? ex2f(fmaf(c0[3], SCL2, biasB)) : 0.0f;
            lsA += p0 + p1;
            lsB += p2 + p3;
            pa0 = packh2(p0, p1);
            pa1 = packh2(p2, p3);
        }
        if (a1) {
            const int ci = nb1 * 8 + 2 * t;
            float p0 = (ci     <= n0) ? ex2f(fmaf(c1[0], SCL2, biasA)) : 0.0f;
            float p1 = (ci + 1 <= n0) ? ex2f(fmaf(c1[1], SCL2, biasA)) : 0.0f;
            float p2 = (ci     <= n0) ? ex2f(fmaf(c1[2], SCL2, biasB)) : 0.0f;
            float p3 = (ci + 1 <= n0) ? ex2f(fmaf(c1[3], SCL2, biasB)) : 0.0f;
            lsA += p0 + p1;
            lsB += p2 + p3;
            pa2 = packh2(p0, p1);
            pa3 = packh2(p2, p3);
        } else {
            pa2 = 0u; pa3 = 0u;
        }

        // QK(nbp+1) ahead of PV(nbp); non-volatile mma lets ptxas interleave.
        float d0[4] = {0, 0, 0, 0}, d1[4] = {0, 0, 0, 0};
        const bool nxt = (nbp + 1 < NBPN) && (2 * (nbp + 1) <= dep);
        if (nxt)
            qk_block(qa, Kt, nbp + 1, (2 * (nbp + 1) + 1 <= dep), d0, d1);

        #pragma unroll
        for (int db2 = 0; db2 < 4; db2++) {
            uint4 vv = Vt[(nbp * 4 + db2) * 32];
            mma16(oacc[2 * db2],     pa0, pa1, pa2, pa3, vv.x, vv.y);
            mma16(oacc[2 * db2 + 1], pa0, pa1, pa2, pa3, vv.z, vv.w);
        }

        #pragma unroll
        for (int i = 0; i < 4; i++) { c0[i] = d0[i]; c1[i] = d1[i]; }
    }
}

// ---------------------------------------------------------------------------
// Main attention: balanced dual-tile warps (R13) + pipeline (R14),
// non-volatile mma. 128 threads = 4 warps; warp w owns depth tiles {w, 7-w}.
// ---------------------------------------------------------------------------
__global__ __launch_bounds__(128, 4)
void attn14(const float* __restrict__ bw, float* __restrict__ out) {
    const int tid  = threadIdx.x;
    const int lane = tid & 31;
    const int w    = tid >> 5;       // 0..3
    const int g    = lane >> 2;
    const int t    = lane & 3;
    const int qtb  = blockIdx.x;
    const int h    = blockIdx.y;
    const int b    = blockIdx.z;
    const int bh   = b * HH + h;
    const int l0   = qtb * 128;

    const float b2s = bw[HH + h] * LOG2E;
    const float b2d = bw[h] * LOG2E;

    const int dep0 = w;              // light tile
    const int dep1 = 7 - w;          // heavy tile
    const int n00  = 8 * dep0 + g;
    const int n01  = 8 * dep1 + g;

    uint32_t qa0[4][4], qa1[4][4];
    {
        const uint4* QA = g_Qh + ((size_t)bh * 256 + qtb * 16 + dep0) * 64 + lane;
        const uint4* QB = QA + 8 * 64;
        uint4 a0 = QA[0], a1 = QA[32], b0 = QB[0], b1 = QB[32];
        qa0[0][0] = a0.x; qa0[0][1] = b0.x; qa0[0][2] = a0.y; qa0[0][3] = b0.y;
        qa0[1][0] = a0.z; qa0[1][1] = b0.z; qa0[1][2] = a0.w; qa0[1][3] = b0.w;
        qa0[2][0] = a1.x; qa0[2][1] = b1.x; qa0[2][2] = a1.y; qa0[2][3] = b1.y;
        qa0[3][0] = a1.z; qa0[3][1] = b1.z; qa0[3][2] = a1.w; qa0[3][3] = b1.w;
    }
    {
        const uint4* QA = g_Qh + ((size_t)bh * 256 + qtb * 16 + dep1) * 64 + lane;
        const uint4* QB = QA + 8 * 64;
        uint4 a0 = QA[0], a1 = QA[32], b0 = QB[0], b1 = QB[32];
        qa1[0][0] = a0.x; qa1[0][1] = b0.x; qa1[0][2] = a0.y; qa1[0][3] = b0.y;
        qa1[1][0] = a0.z; qa1[1][1] = b0.z; qa1[1][2] = a0.w; qa1[1][3] = b0.w;
        qa1[2][0] = a1.x; qa1[2][1] = b1.x; qa1[2][2] = a1.y; qa1[2][3] = b1.y;
        qa1[3][0] = a1.z; qa1[3][1] = b1.z; qa1[3][2] = a1.w; qa1[3][3] = b1.w;
    }

    float o0[8][4], o1[8][4];
    #pragma unroll
    for (int db = 0; db < 8; db++)
        #pragma unroll
        for (int i = 0; i < 4; i++) { o0[db][i] = 0.0f; o1[db][i] = 0.0f; }
    float lsA0 = 0.0f, lsB0 = 0.0f, lsA1 = 0.0f, lsB1 = 0.0f;

    const uint4* Kf0 = g_Kh + (size_t)bh * 256 * 64 + lane;
    const uint4* Vf0 = g_Vh + (size_t)bh * NKT * 512 + lane;

    for (int kt = 0; kt < NKT; kt++) {
        const uint4* Kt = Kf0 + (size_t)kt * 8 * 64;
        const uint4* Vt = Vf0 + (size_t)kt * 512;
        const float biasA = (kt == 2 * qtb)     ? b2s : b2d;
        const float biasB = (kt == 2 * qtb + 1) ? b2s : b2d;

        tile_kt_pipe<2>(dep0, n00, qa0, Kt, Vt, biasA, biasB, t, o0, lsA0, lsB0);
        tile_kt_pipe<4>(dep1, n01, qa1, Kt, Vt, biasA, biasB, t, o1, lsA1, lsB1);
    }

    #pragma unroll
    for (int ti = 0; ti < 2; ti++) {
        float lsA = ti ? lsA1 : lsA0;
        float lsB = ti ? lsB1 : lsB0;
        lsA += __shfl_xor_sync(0xffffffffu, lsA, 1);
        lsA += __shfl_xor_sync(0xffffffffu, lsA, 2);
        lsB += __shfl_xor_sync(0xffffffffu, lsB, 1);
        lsB += __shfl_xor_sync(0xffffffffu, lsB, 2);
        const float invA = 1.0f / lsA;
        const float invB = 1.0f / lsB;
        float (*oacc)[4] = ti ? o1 : o0;
        const int dep = ti ? dep1 : dep0;
        const int rowA = l0 + 8 * dep + g;
        const int rowB = rowA + 64;
        #pragma unroll
        for (int db = 0; db < 8; db++) {
            float2 v0;
            v0.x = oacc[db][0] * invA;
            v0.y = oacc[db][1] * invA;
            *(float2*)(out + (((size_t)(b * LL + rowA)) * HH + h) * EE + db * 8 + 2 * t) = v0;
            float2 v1;
            v1.x = oacc[db][2] * invB;
            v1.y = oacc[db][3] * invB;
            *(float2*)(out + (((size_t)(b * LL + rowB)) * HH + h) * EE + db * 8 + 2 * t) = v1;
        }
    }
}

// ---------------------------------------------------------------------------
extern "C" void kernel_launch(void* const* d_in, const int* in_sizes, int n_in,
                              void* d_out, int out_size) {
    const float* q  = (const float*)d_in[0];
    const float* k  = (const float*)d_in[1];
    const float* v  = (const float*)d_in[2];
    const float* bw = (const float*)d_in[3];
    float* out = (float*)d_out;

    prep_kernel<<<dim3(NKT, HH, BB), 256>>>(q, k, v);

    dim3 grid(LL / 128, HH, BB);
    attn14<<<grid, 128>>>(bw, out);
}